// round 15
// baseline (speedup 1.0000x reference)
#include <cuda_runtime.h>

#define BB 4
#define NN 50000
#define DD 256
#define EE 800000
#define CAP 128                    // fixed bucket capacity per node
#define TAU_MIN 0.001f
#define MAX_CORR 0.15f
#define FILLB (EE / 256)           // 3125 fill blocks
#define PREDB (BB * NN / 8)        // 25000 pred blocks (warp per row)
// fill:pred block ratio is exactly 1:8 -> interleave every 9th block.
#define FATB  (FILLB + PREDB)      // 28125

// Ping-pong positions, layout x[node][batch] (4 batches = 64B contiguous).
__device__ float4 g_x0[NN * BB];
__device__ float4 g_x1[NN * BB];
// Fixed-capacity adjacency buckets: adj[node*CAP + slot] = {other, L0 bits}.
__device__ int  g_cnt[NN];
__device__ int2 g_adj[NN * CAP];

// ---------------------------------------------------------------------------
// Fat kernel with INTERLEAVED roles: blocks with blockIdx%9==8 build the
// adjacency buckets (L2/atomic-bound); the rest compute
// x_pred = kp + tau*(ht @ W + b) (DRAM-bound). Interleaving keeps both
// populations resident on the SMs simultaneously (ascending block scheduling
// would otherwise serialize the two phases).
// ---------------------------------------------------------------------------
__global__ __launch_bounds__(256) void fat_kernel(
    const float* __restrict__ kp, const float* __restrict__ ts,
    const float4* __restrict__ ht4, const float* __restrict__ hw,
    const float* __restrict__ hb, const int* __restrict__ ei,
    const float* __restrict__ rl, float4* __restrict__ x,
    int* __restrict__ cnt, int2* __restrict__ adj)
{
    __shared__ float4 sw0[DD / 4], sw1[DD / 4], sw2[DD / 4];
    int tid = threadIdx.x;
    int bi = blockIdx.x;
    int fidx = bi / 9;
    bool is_fill = ((bi % 9) == 8);

    if (is_fill) {
        // ---- fill branch (exactly EE threads across 3125 blocks) ----
        int e = fidx * 256 + tid;
        int s = __ldg(&ei[e]);
        int d = __ldg(&ei[EE + e]);
        int lb = __float_as_int(__ldg(&rl[e]));
        int ps = atomicAdd(&cnt[s], 1);
        if (ps < CAP) adj[s * CAP + ps] = make_int2(d, lb);
        int pd = atomicAdd(&cnt[d], 1);
        if (pd < CAP) adj[d * CAP + pd] = make_int2(s, lb);
        return;
    }

    // ---- pred branch: warp per (b,n) row ----
    int pidx = bi - fidx;               // contiguous pred block id, 0..24999
    if (tid < DD) {
        ((float*)sw0)[tid] = hw[tid * 3 + 0];
        ((float*)sw1)[tid] = hw[tid * 3 + 1];
        ((float*)sw2)[tid] = hw[tid * 3 + 2];
    }
    __syncthreads();

    int warp = (pidx * 256 + tid) >> 5;   // exact: < BB*NN
    int lane = tid & 31;

    const float4* r4 = ht4 + (size_t)warp * (DD / 4);
    float4 v1 = __ldg(&r4[lane]);
    float4 v2 = __ldg(&r4[32 + lane]);
    float4 u0a = sw0[lane], u0b = sw0[32 + lane];
    float4 u1a = sw1[lane], u1b = sw1[32 + lane];
    float4 u2a = sw2[lane], u2b = sw2[32 + lane];

    float a0 = v1.x * u0a.x, a1 = v1.x * u1a.x, a2 = v1.x * u2a.x;
    a0 = fmaf(v1.y, u0a.y, a0); a1 = fmaf(v1.y, u1a.y, a1); a2 = fmaf(v1.y, u2a.y, a2);
    a0 = fmaf(v1.z, u0a.z, a0); a1 = fmaf(v1.z, u1a.z, a1); a2 = fmaf(v1.z, u2a.z, a2);
    a0 = fmaf(v1.w, u0a.w, a0); a1 = fmaf(v1.w, u1a.w, a1); a2 = fmaf(v1.w, u2a.w, a2);
    a0 = fmaf(v2.x, u0b.x, a0); a1 = fmaf(v2.x, u1b.x, a1); a2 = fmaf(v2.x, u2b.x, a2);
    a0 = fmaf(v2.y, u0b.y, a0); a1 = fmaf(v2.y, u1b.y, a1); a2 = fmaf(v2.y, u2b.y, a2);
    a0 = fmaf(v2.z, u0b.z, a0); a1 = fmaf(v2.z, u1b.z, a1); a2 = fmaf(v2.z, u2b.z, a2);
    a0 = fmaf(v2.w, u0b.w, a0); a1 = fmaf(v2.w, u1b.w, a1); a2 = fmaf(v2.w, u2b.w, a2);

#pragma unroll
    for (int off = 16; off > 0; off >>= 1) {
        a0 += __shfl_down_sync(0xffffffffu, a0, off);
        a1 += __shfl_down_sync(0xffffffffu, a1, off);
        a2 += __shfl_down_sync(0xffffffffu, a2, off);
    }
    if (lane == 0) {
        int b = warp / NN;
        int n = warp - b * NN;
        float tau = fmaxf(1.0f - __ldg(&ts[b]), TAU_MIN);
        float4 r;
        r.x = kp[3 * warp + 0] + tau * (a0 + __ldg(&hb[0]));
        r.y = kp[3 * warp + 1] + tau * (a1 + __ldg(&hb[1]));
        r.z = kp[3 * warp + 2] + tau * (a2 + __ldg(&hb[2]));
        r.w = 0.0f;
        x[n * BB + b] = r;
    }
}

// ---------------------------------------------------------------------------
// XPBD Jacobi iteration: TWO warps per node. Warp half h handles batches
// {2h, 2h+1}; lane = jl*2 + (b - 2h), jl = 16 neighbor slots. Pair-lanes
// gather 32B-aligned halves of a node record (full sector utilization).
// Halved per-warp serial chain + 2x warp count = better latency absorption.
// Math: sc = (L0 - d2*r)*0.5f*r with r = rsqrtf(max(d2,1e-38)); one MUFU,
// no division; fp-identical at both endpoints (odd symmetry of clip(sc*d)).
// FINAL=true fuses v_eff = (x - kp)/tau.
// ---------------------------------------------------------------------------
#define EDGE_ACC(A)                                                         \
    do {                                                                    \
        float dx = xs.x - q##A.x;                                           \
        float dy = xs.y - q##A.y;                                           \
        float dz = xs.z - q##A.z;                                           \
        float d2 = fmaf(dx, dx, fmaf(dy, dy, dz * dz));                     \
        float r = rsqrtf(fmaxf(d2, 1e-38f));                                \
        float L0 = __int_as_float(a##A.y);                                  \
        float sc = (L0 - d2 * r) * 0.5f * r;                                \
        ax += fminf(fmaxf(sc * dx, -MAX_CORR), MAX_CORR);                   \
        ay += fminf(fmaxf(sc * dy, -MAX_CORR), MAX_CORR);                   \
        az += fminf(fmaxf(sc * dz, -MAX_CORR), MAX_CORR);                   \
    } while (0)

template <bool FINAL>
__global__ __launch_bounds__(256) void iter_kernel(
    const float4* __restrict__ xc, float4* __restrict__ xn,
    const int* __restrict__ cnt, const int2* __restrict__ adj,
    const float* __restrict__ kp, const float* __restrict__ ts,
    float* __restrict__ out)
{
    int w = (blockIdx.x * blockDim.x + threadIdx.x) >> 5;
    if (w >= 2 * NN) return;
    int n = w >> 1;                 // node
    int h = w & 1;                  // batch-pair half
    int lane = threadIdx.x & 31;
    int b = 2 * h + (lane & 1);     // batch 2h or 2h+1
    int jl = lane >> 1;             // neighbor slot 0..15

    float4 xs = __ldg(&xc[n * BB + b]);
    int deg = min(__ldg(&cnt[n]), CAP);
    const int2* ab = adj + n * CAP;

    float ax = 0.f, ay = 0.f, az = 0.f;
    int j = jl;

    // 2-wide batches over slot stride 16: 4 independent loads in flight.
    while (j + 16 < deg) {
        int2 a0 = __ldg(&ab[j]);
        int2 a1 = __ldg(&ab[j + 16]);
        float4 q0 = __ldg(&xc[a0.x * BB + b]);
        float4 q1 = __ldg(&xc[a1.x * BB + b]);
        EDGE_ACC(0); EDGE_ACC(1);
        j += 32;
    }
    if (j < deg) {                  // at most one leftover entry per lane
        int2 a0 = __ldg(&ab[j]);
        float4 q0 = __ldg(&xc[a0.x * BB + b]);
        EDGE_ACC(0);
    }

    // Reduce over the 16 neighbor slots (lanes stride 2, same b).
#pragma unroll
    for (int o = 16; o >= 2; o >>= 1) {
        ax += __shfl_xor_sync(0xffffffffu, ax, o);
        ay += __shfl_xor_sync(0xffffffffu, ay, o);
        az += __shfl_xor_sync(0xffffffffu, az, o);
    }
    if (jl == 0) {                  // lanes 0 and 1 (one per batch)
        float rx = xs.x + ax;
        float ry = xs.y + ay;
        float rz = xs.z + az;
        if (FINAL) {
            int idx = b * NN + n;
            float tau = fmaxf(1.0f - __ldg(&ts[b]), TAU_MIN);
            out[3 * idx + 0] = (rx - kp[3 * idx + 0]) / tau;
            out[3 * idx + 1] = (ry - kp[3 * idx + 1]) / tau;
            out[3 * idx + 2] = (rz - kp[3 * idx + 2]) / tau;
        } else {
            float4 r;
            r.x = rx; r.y = ry; r.z = rz; r.w = 0.0f;
            xn[n * BB + b] = r;
        }
    }
}

extern "C" void kernel_launch(void* const* d_in, const int* in_sizes, int n_in,
                              void* d_out, int out_size)
{
    const float* kp = (const float*)d_in[0];
    const float* ts = (const float*)d_in[1];
    const float* ht = (const float*)d_in[2];
    const float* hw = (const float*)d_in[3];
    const float* hb = (const float*)d_in[4];
    const int*   ei = (const int*)d_in[5];
    const float* rl = (const float*)d_in[6];
    float* out = (float*)d_out;

    float4 *x0, *x1;
    int *cnt;
    int2 *adj;
    cudaGetSymbolAddress((void**)&x0, g_x0);
    cudaGetSymbolAddress((void**)&x1, g_x1);
    cudaGetSymbolAddress((void**)&cnt, g_cnt);
    cudaGetSymbolAddress((void**)&adj, g_adj);

    // Zero bucket counters, then run role-interleaved [fill | pred] grid.
    cudaMemsetAsync(cnt, 0, NN * sizeof(int));
    fat_kernel<<<FATB, 256>>>(kp, ts, (const float4*)ht, hw, hb,
                              ei, rl, x0, cnt, adj);

    // 4 Jacobi XPBD iterations (2 warps/node); final fuses v_eff epilogue.
    const int T = 256;
    int ib = (2 * NN * 32 + T - 1) / T;   // 12500 blocks
    iter_kernel<false><<<ib, T>>>(x0, x1, cnt, adj, kp, ts, out);
    iter_kernel<false><<<ib, T>>>(x1, x0, cnt, adj, kp, ts, out);
    iter_kernel<false><<<ib, T>>>(x0, x1, cnt, adj, kp, ts, out);
    iter_kernel<true><<<ib, T>>>(x1, x0, cnt, adj, kp, ts, out);
}

// round 16
// speedup vs baseline: 1.1704x; 1.1704x over previous
#include <cuda_runtime.h>

#define BB 4
#define NN 50000
#define DD 256
#define EE 800000
#define CAP 128                    // fixed bucket capacity per node
#define TAU_MIN 0.001f
#define MAX_CORR 0.15f
#define FILLB (EE / 256)           // 3125 fill blocks
#define PREDB (BB * NN / 8)        // 25000 pred blocks (warp per row)
// fill:pred block ratio is exactly 1:8 -> interleave every 9th block.
#define FATB  (FILLB + PREDB)      // 28125

// Ping-pong positions, layout x[node][batch] (4 batches = 64B contiguous).
__device__ float4 g_x0[NN * BB];
__device__ float4 g_x1[NN * BB];
// Fixed-capacity adjacency buckets: adj[node*CAP + slot] = {other, L0 bits}.
__device__ int  g_cnt[NN];
__device__ int2 g_adj[NN * CAP];

// ---------------------------------------------------------------------------
// Fat kernel with INTERLEAVED roles: blocks with blockIdx%9==8 build the
// adjacency buckets (L2/atomic-bound); the rest compute
// x_pred = kp + tau*(ht @ W + b) (DRAM-bound). Interleaving keeps both
// populations co-resident on the SMs (R15 measured: -10us vs segregated).
// ---------------------------------------------------------------------------
__global__ __launch_bounds__(256) void fat_kernel(
    const float* __restrict__ kp, const float* __restrict__ ts,
    const float4* __restrict__ ht4, const float* __restrict__ hw,
    const float* __restrict__ hb, const int* __restrict__ ei,
    const float* __restrict__ rl, float4* __restrict__ x,
    int* __restrict__ cnt, int2* __restrict__ adj)
{
    __shared__ float4 sw0[DD / 4], sw1[DD / 4], sw2[DD / 4];
    int tid = threadIdx.x;
    int bi = blockIdx.x;
    int fidx = bi / 9;
    bool is_fill = ((bi % 9) == 8);

    if (is_fill) {
        // ---- fill branch (exactly EE threads across 3125 blocks) ----
        int e = fidx * 256 + tid;
        int s = __ldg(&ei[e]);
        int d = __ldg(&ei[EE + e]);
        int lb = __float_as_int(__ldg(&rl[e]));
        int ps = atomicAdd(&cnt[s], 1);
        if (ps < CAP) adj[s * CAP + ps] = make_int2(d, lb);
        int pd = atomicAdd(&cnt[d], 1);
        if (pd < CAP) adj[d * CAP + pd] = make_int2(s, lb);
        return;
    }

    // ---- pred branch: warp per (b,n) row ----
    int pidx = bi - fidx;               // contiguous pred block id, 0..24999
    if (tid < DD) {
        ((float*)sw0)[tid] = hw[tid * 3 + 0];
        ((float*)sw1)[tid] = hw[tid * 3 + 1];
        ((float*)sw2)[tid] = hw[tid * 3 + 2];
    }
    __syncthreads();

    int warp = (pidx * 256 + tid) >> 5;   // exact: < BB*NN
    int lane = tid & 31;

    const float4* r4 = ht4 + (size_t)warp * (DD / 4);
    float4 v1 = __ldg(&r4[lane]);
    float4 v2 = __ldg(&r4[32 + lane]);
    float4 u0a = sw0[lane], u0b = sw0[32 + lane];
    float4 u1a = sw1[lane], u1b = sw1[32 + lane];
    float4 u2a = sw2[lane], u2b = sw2[32 + lane];

    float a0 = v1.x * u0a.x, a1 = v1.x * u1a.x, a2 = v1.x * u2a.x;
    a0 = fmaf(v1.y, u0a.y, a0); a1 = fmaf(v1.y, u1a.y, a1); a2 = fmaf(v1.y, u2a.y, a2);
    a0 = fmaf(v1.z, u0a.z, a0); a1 = fmaf(v1.z, u1a.z, a1); a2 = fmaf(v1.z, u2a.z, a2);
    a0 = fmaf(v1.w, u0a.w, a0); a1 = fmaf(v1.w, u1a.w, a1); a2 = fmaf(v1.w, u2a.w, a2);
    a0 = fmaf(v2.x, u0b.x, a0); a1 = fmaf(v2.x, u1b.x, a1); a2 = fmaf(v2.x, u2b.x, a2);
    a0 = fmaf(v2.y, u0b.y, a0); a1 = fmaf(v2.y, u1b.y, a1); a2 = fmaf(v2.y, u2b.y, a2);
    a0 = fmaf(v2.z, u0b.z, a0); a1 = fmaf(v2.z, u1b.z, a1); a2 = fmaf(v2.z, u2b.z, a2);
    a0 = fmaf(v2.w, u0b.w, a0); a1 = fmaf(v2.w, u1b.w, a1); a2 = fmaf(v2.w, u2b.w, a2);

#pragma unroll
    for (int off = 16; off > 0; off >>= 1) {
        a0 += __shfl_down_sync(0xffffffffu, a0, off);
        a1 += __shfl_down_sync(0xffffffffu, a1, off);
        a2 += __shfl_down_sync(0xffffffffu, a2, off);
    }
    if (lane == 0) {
        int b = warp / NN;
        int n = warp - b * NN;
        float tau = fmaxf(1.0f - __ldg(&ts[b]), TAU_MIN);
        float4 r;
        r.x = kp[3 * warp + 0] + tau * (a0 + __ldg(&hb[0]));
        r.y = kp[3 * warp + 1] + tau * (a1 + __ldg(&hb[1]));
        r.z = kp[3 * warp + 2] + tau * (a2 + __ldg(&hb[2]));
        r.w = 0.0f;
        x[n * BB + b] = r;
    }
}

// ---------------------------------------------------------------------------
// XPBD Jacobi iteration: ONE warp per node (R14 shape — best measured).
// Lane = jl*4 + b: 8 neighbor slots x 4 batches. Uniform trip count
// T = ceil(deg/32) across the warp; out-of-range entries load a clamped
// in-bounds slot (usually L1-hit) and mask their scale to 0 — no divergent
// tail, every trip runs the full 4-deep load pipeline.
// Math: sc = (L0 - d2*r)*0.5f*r, r = rsqrtf(max(d2,1e-38)): one MUFU, no
// division; fp-identical at both endpoints (odd symmetry of clip(sc*d)).
// FINAL=true fuses v_eff = (x - kp)/tau.
// ---------------------------------------------------------------------------
#define EDGE_ACC(A)                                                         \
    do {                                                                    \
        float dx = xs.x - q##A.x;                                           \
        float dy = xs.y - q##A.y;                                           \
        float dz = xs.z - q##A.z;                                           \
        float d2 = fmaf(dx, dx, fmaf(dy, dy, dz * dz));                     \
        float r = rsqrtf(fmaxf(d2, 1e-38f));                                \
        float L0 = __int_as_float(a##A.y);                                  \
        float sc = (L0 - d2 * r) * 0.5f * r;                                \
        sc = v##A ? sc : 0.0f;                                              \
        ax += fminf(fmaxf(sc * dx, -MAX_CORR), MAX_CORR);                   \
        ay += fminf(fmaxf(sc * dy, -MAX_CORR), MAX_CORR);                   \
        az += fminf(fmaxf(sc * dz, -MAX_CORR), MAX_CORR);                   \
    } while (0)

template <bool FINAL>
__global__ __launch_bounds__(256) void iter_kernel(
    const float4* __restrict__ xc, float4* __restrict__ xn,
    const int* __restrict__ cnt, const int2* __restrict__ adj,
    const float* __restrict__ kp, const float* __restrict__ ts,
    float* __restrict__ out)
{
    int gw = (blockIdx.x * blockDim.x + threadIdx.x) >> 5;  // node
    if (gw >= NN) return;
    int lane = threadIdx.x & 31;
    int b = lane & 3;
    int jl = lane >> 2;     // neighbor slot 0..7

    float4 xs = __ldg(&xc[gw * BB + b]);
    int deg = min(__ldg(&cnt[gw]), CAP);
    const int2* ab = adj + gw * CAP;
    int dm1 = deg - 1;      // deg==0 => T==0, loop skipped
    int T = (deg + 31) >> 5;

    float ax = 0.f, ay = 0.f, az = 0.f;

    for (int t = 0; t < T; ++t) {
        int j = jl + (t << 5);
        bool v0 = (j      < deg);
        bool v1 = (j + 8  < deg);
        bool v2 = (j + 16 < deg);
        bool v3 = (j + 24 < deg);
        int j0 = min(j,      dm1);
        int j1 = min(j + 8,  dm1);
        int j2 = min(j + 16, dm1);
        int j3 = min(j + 24, dm1);
        int2 a0 = __ldg(&ab[j0]);
        int2 a1 = __ldg(&ab[j1]);
        int2 a2 = __ldg(&ab[j2]);
        int2 a3 = __ldg(&ab[j3]);
        float4 q0 = __ldg(&xc[a0.x * BB + b]);
        float4 q1 = __ldg(&xc[a1.x * BB + b]);
        float4 q2 = __ldg(&xc[a2.x * BB + b]);
        float4 q3 = __ldg(&xc[a3.x * BB + b]);
        EDGE_ACC(0); EDGE_ACC(1); EDGE_ACC(2); EDGE_ACC(3);
    }

    // Reduce over the 8 neighbor slots (stride-4 lanes, same b).
#pragma unroll
    for (int o = 16; o >= 4; o >>= 1) {
        ax += __shfl_xor_sync(0xffffffffu, ax, o);
        ay += __shfl_xor_sync(0xffffffffu, ay, o);
        az += __shfl_xor_sync(0xffffffffu, az, o);
    }
    if (jl == 0) {
        float rx = xs.x + ax;
        float ry = xs.y + ay;
        float rz = xs.z + az;
        if (FINAL) {
            int idx = b * NN + gw;
            float tau = fmaxf(1.0f - __ldg(&ts[b]), TAU_MIN);
            out[3 * idx + 0] = (rx - kp[3 * idx + 0]) / tau;
            out[3 * idx + 1] = (ry - kp[3 * idx + 1]) / tau;
            out[3 * idx + 2] = (rz - kp[3 * idx + 2]) / tau;
        } else {
            float4 r;
            r.x = rx; r.y = ry; r.z = rz; r.w = 0.0f;
            xn[gw * BB + b] = r;
        }
    }
}

extern "C" void kernel_launch(void* const* d_in, const int* in_sizes, int n_in,
                              void* d_out, int out_size)
{
    const float* kp = (const float*)d_in[0];
    const float* ts = (const float*)d_in[1];
    const float* ht = (const float*)d_in[2];
    const float* hw = (const float*)d_in[3];
    const float* hb = (const float*)d_in[4];
    const int*   ei = (const int*)d_in[5];
    const float* rl = (const float*)d_in[6];
    float* out = (float*)d_out;

    float4 *x0, *x1;
    int *cnt;
    int2 *adj;
    cudaGetSymbolAddress((void**)&x0, g_x0);
    cudaGetSymbolAddress((void**)&x1, g_x1);
    cudaGetSymbolAddress((void**)&cnt, g_cnt);
    cudaGetSymbolAddress((void**)&adj, g_adj);

    // Zero bucket counters, then run role-interleaved [fill | pred] grid.
    cudaMemsetAsync(cnt, 0, NN * sizeof(int));
    fat_kernel<<<FATB, 256>>>(kp, ts, (const float4*)ht, hw, hb,
                              ei, rl, x0, cnt, adj);

    // 4 Jacobi XPBD iterations (1 warp/node); final fuses v_eff epilogue.
    const int T = 256;
    int ib = (NN * 32 + T - 1) / T;   // 6250 blocks
    iter_kernel<false><<<ib, T>>>(x0, x1, cnt, adj, kp, ts, out);
    iter_kernel<false><<<ib, T>>>(x1, x0, cnt, adj, kp, ts, out);
    iter_kernel<false><<<ib, T>>>(x0, x1, cnt, adj, kp, ts, out);
    iter_kernel<true><<<ib, T>>>(x1, x0, cnt, adj, kp, ts, out);
}